// round 1
// baseline (speedup 1.0000x reference)
#include <cuda_runtime.h>
#include <math.h>

#define B_     4
#define NCH    32
#define T_FULL 65536
#define T_IN   8192
#define L_     256
#define HOP_   256
#define H_     64
#define KC_    24576

// ---- scratch (device globals; no allocation allowed) ----
__device__ float g_H [B_*NCH*T_FULL];   // running hidden state (33.5 MB)
__device__ float g_C [B_*NCH*T_FULL];   // dilated-conv output  (33.5 MB)
__device__ float g_F0[B_*H_*L_];
__device__ float g_F1[B_*H_*L_];
__device__ float g_KT[B_*L_*KC_];       // predicted kernels, TRANSPOSED [b][l][kc] (100 MB)
__device__ float g_BS[B_*256*L_];       // predicted biases [b][bc][l]

__device__ __forceinline__ float lrelu(float x){ return x >= 0.f ? x : 0.2f*x; }

// ============================================================
// K1: conv_transpose1d  (stride 8, K=16, pad 4)
// y[b,o,t] = sum_i w[i,o,r]*x[i,j1] + w[i,o,r+8]*x[i,j1-1],
//   r=(t+4)%8, j1=(t+4)/8.  Thread = (o, r) phase, 32 t's each.
// ============================================================
__global__ void k_convT(const float* __restrict__ x, const float* __restrict__ w,
                        const float* __restrict__ bias){
    int b  = blockIdx.y;
    int t0 = blockIdx.x * 256;
    int tid = threadIdx.x;
    int r = tid & 7, o = tid >> 3;
    __shared__ float xs[NCH*36];
    const float* xb = x + b*NCH*T_IN;
    int jbase = t0/8 - 1;
    for (int idx = tid; idx < NCH*34; idx += 256){
        int c = idx / 34, p = idx % 34;
        int j = jbase + p;
        xs[c*36 + p] = (j >= 0 && j < T_IN) ? xb[c*T_IN + j] : 0.f;
    }
    __syncthreads();
    float acc[32];
    float bv = bias[o];
    #pragma unroll
    for (int s = 0; s < 32; s++) acc[s] = bv;
    int off = (r + 4) & 7;
    int e   = (off >= 4) ? 1 : 0;
    for (int i = 0; i < NCH; i++){
        float w1 = w[(i*32 + o)*16 + r];
        float w2 = w[(i*32 + o)*16 + r + 8];
        const float* xr = &xs[i*36 + e];
        float vp = xr[0];
        #pragma unroll
        for (int s = 0; s < 32; s++){
            float v = xr[s + 1];
            acc[s] += w1*v + w2*vp;
            vp = v;
        }
    }
    float* out = &g_H[(b*NCH + o)*T_FULL];
    #pragma unroll
    for (int s = 0; s < 32; s++) out[t0 + off + 8*s] = acc[s];
}

// ============================================================
// K2: spectrogram input conv (100->64, K=5, pad 2)
// ============================================================
__global__ void k_spec(const float* __restrict__ spec, const float* __restrict__ w,
                       const float* __restrict__ bias){
    int b = blockIdx.x, h = blockIdx.y, l = threadIdx.x;
    const float* sp = spec + b*100*L_;
    const float* wp = w + h*500;
    float acc = bias[h];
    for (int c = 0; c < 100; c++){
        #pragma unroll
        for (int k = 0; k < 5; k++){
            int t = l + k - 2;
            if (t >= 0 && t < L_) acc += wp[c*5 + k] * sp[c*L_ + t];
        }
    }
    g_F0[(b*H_ + h)*L_ + l] = acc;
}

// ============================================================
// K3: residual-block conv (64->64, K=3, pad 1), lrelu fused.
// phase 0: F1 = lrelu(conv(F0));  phase 1: F0 = lrelu(conv(F1)) + F0
// ============================================================
__global__ void k_res(const float* __restrict__ w, const float* __restrict__ bias, int phase){
    int b = blockIdx.x, h = blockIdx.y, l = threadIdx.x;
    const float* in = phase ? &g_F1[b*H_*L_] : &g_F0[b*H_*L_];
    const float* wp = w + h*H_*3;
    float acc = bias[h];
    for (int c = 0; c < H_; c++){
        #pragma unroll
        for (int k = 0; k < 3; k++){
            int t = l + k - 1;
            if (t >= 0 && t < L_) acc += wp[c*3 + k] * in[c*L_ + t];
        }
    }
    acc = lrelu(acc);
    if (phase) g_F0[(b*H_ + h)*L_ + l] = acc + g_F0[(b*H_ + h)*L_ + l];
    else       g_F1[(b*H_ + h)*L_ + l] = acc;
}

// ============================================================
// K5: kern conv as GEMM:  out[b][l][kc] (TRANSPOSED store)
//   = sum_r A[kc][r] * X[r][l] + kern_b[kc],  r = h*3+k (K=192)
//   X[r][l] = F0[b][h][l+k-1]  (im2col built on the fly)
// 64x64 tile, BK=16, 4x4 micro-tile per thread.
// ============================================================
__global__ void k_kern_gemm(const float* __restrict__ A, const float* __restrict__ Ab){
    int b   = blockIdx.z;
    int kc0 = blockIdx.x * 64;
    int l0  = blockIdx.y * 64;
    int tid = threadIdx.x;
    int ty = tid / 16, tx = tid % 16;
    __shared__ float As[16][64];
    __shared__ float Xs[16][64];
    const float* F = &g_F0[b*H_*L_];
    float acc[4][4];
    #pragma unroll
    for (int a = 0; a < 4; a++)
        #pragma unroll
        for (int j = 0; j < 4; j++) acc[a][j] = 0.f;
    int mm = tid/4, rr4 = (tid%4)*4;       // A-load mapping
    int lrr = tid/16, lj = (tid%16)*4;     // X-load mapping
    for (int bk = 0; bk < 12; bk++){
        int r0 = bk*16;
        float4 av = *(const float4*)&A[(kc0 + mm)*192 + r0 + rr4];
        As[rr4+0][mm] = av.x; As[rr4+1][mm] = av.y;
        As[rr4+2][mm] = av.z; As[rr4+3][mm] = av.w;
        {
            int r = r0 + lrr;
            int hh = r/3, k = r%3;
            #pragma unroll
            for (int q = 0; q < 4; q++){
                int l = l0 + lj + q;
                int t = l + k - 1;
                Xs[lrr][lj+q] = (t >= 0 && t < L_) ? F[hh*L_ + t] : 0.f;
            }
        }
        __syncthreads();
        #pragma unroll
        for (int kk = 0; kk < 16; kk++){
            float4 a4 = *(const float4*)&As[kk][ty*4];
            float4 x4 = *(const float4*)&Xs[kk][tx*4];
            float av_[4] = {a4.x, a4.y, a4.z, a4.w};
            float xv_[4] = {x4.x, x4.y, x4.z, x4.w};
            #pragma unroll
            for (int a = 0; a < 4; a++)
                #pragma unroll
                for (int j = 0; j < 4; j++) acc[a][j] += av_[a]*xv_[j];
        }
        __syncthreads();
    }
    #pragma unroll
    for (int j = 0; j < 4; j++){
        int l = l0 + tx*4 + j;
        float4 ov;
        ov.x = acc[0][j] + Ab[kc0 + ty*4 + 0];
        ov.y = acc[1][j] + Ab[kc0 + ty*4 + 1];
        ov.z = acc[2][j] + Ab[kc0 + ty*4 + 2];
        ov.w = acc[3][j] + Ab[kc0 + ty*4 + 3];
        *(float4*)&g_KT[(b*L_ + l)*KC_ + kc0 + ty*4] = ov;
    }
}

// ============================================================
// K6: bias conv (64->256, K=3, pad 1) -> g_BS[b][bc][l]
// ============================================================
__global__ void k_biasconv(const float* __restrict__ w, const float* __restrict__ bias){
    int b = blockIdx.x, bc = blockIdx.y, l = threadIdx.x;
    const float* in = &g_F0[b*H_*L_];
    const float* wp = w + bc*H_*3;
    float acc = bias[bc];
    for (int c = 0; c < H_; c++){
        #pragma unroll
        for (int k = 0; k < 3; k++){
            int t = l + k - 1;
            if (t >= 0 && t < L_) acc += wp[c*3 + k] * in[c*L_ + t];
        }
    }
    g_BS[(b*256 + bc)*L_ + l] = acc;
}

// ============================================================
// K7: fused lrelu -> dilated conv (32->32,K=3,pad d) -> lrelu into g_C
// Block = (b, 128-sample tile). Thread computes 8 o x 4 t.
// ============================================================
__global__ void k_dconv(const float* __restrict__ w, const float* __restrict__ bias, int d){
    int b  = blockIdx.y;
    int t0 = blockIdx.x * 128;
    int tid = threadIdx.x;
    __shared__ float xs[NCH*184];           // 128 + 2*27 max, padded stride 184
    __shared__ float ws[3*NCH*NCH];         // [k][i][o]
    int W = 128 + 2*d;
    const float* Hb = &g_H[b*NCH*T_FULL];
    for (int idx = tid; idx < NCH*W; idx += 128){
        int c = idx / W, p = idx % W;
        int t = t0 - d + p;
        xs[c*184 + p] = (t >= 0 && t < T_FULL) ? lrelu(Hb[c*T_FULL + t]) : 0.f;
    }
    for (int idx = tid; idx < 3072; idx += 128){
        int o = idx / 96, rem = idx % 96;
        int i = rem / 3, k = rem % 3;
        ws[k*1024 + i*32 + o] = w[idx];     // lvc_w[o][i][k] -> [k][i][o]
    }
    __syncthreads();
    int o0 = (tid >> 5) * 8;
    int tl = (tid & 31) * 4;
    float acc[8][4];
    #pragma unroll
    for (int a = 0; a < 8; a++){
        float bv = bias[o0 + a];
        #pragma unroll
        for (int j = 0; j < 4; j++) acc[a][j] = bv;
    }
    for (int i = 0; i < NCH; i++){
        #pragma unroll
        for (int k = 0; k < 3; k++){
            float xv[4];
            #pragma unroll
            for (int j = 0; j < 4; j++) xv[j] = xs[i*184 + tl + j + k*d];
            float4 w0 = *(const float4*)&ws[k*1024 + i*32 + o0];
            float4 w1 = *(const float4*)&ws[k*1024 + i*32 + o0 + 4];
            float wv[8] = {w0.x,w0.y,w0.z,w0.w,w1.x,w1.y,w1.z,w1.w};
            #pragma unroll
            for (int a = 0; a < 8; a++)
                #pragma unroll
                for (int j = 0; j < 4; j++) acc[a][j] += wv[a]*xv[j];
        }
    }
    float* Cb = &g_C[b*NCH*T_FULL];
    #pragma unroll
    for (int a = 0; a < 8; a++)
        #pragma unroll
        for (int j = 0; j < 4; j++)
            Cb[(o0 + a)*T_FULL + t0 + tl + j] = lrelu(acc[a][j]);
}

// ============================================================
// K8: location-variable conv + bias + gating + residual (fused)
// Block = (b, segment l, half of 128 samples). Thread: 8 oc x 4 s,
// computing BOTH gate halves (o and o+32) -> 64 accumulators.
// out[b,oc,t] = sigmoid(lvc_o) * tanh(lvc_{o+32}) + H[b,oc,t]
// ============================================================
__global__ void k_lvc(int layer, float* __restrict__ outp){
    int b  = blockIdx.z;
    int l  = blockIdx.x;
    int h0 = blockIdx.y * 128;
    int tid = threadIdx.x;
    __shared__ float xs[NCH*132];   // 130 window, padded stride 132 (16B-aligned rows)
    __shared__ float ksh[6144];     // [k][c][o]
    const float* Cb  = &g_C[b*NCH*T_FULL];
    const float* KTb = &g_KT[(b*L_ + l)*KC_ + layer*6144];
    int tseg = l*HOP_;
    for (int idx = tid; idx < NCH*130; idx += 128){
        int c = idx / 130, p = idx % 130;
        int t = tseg + h0 - 1 + p;
        xs[c*132 + p] = (t >= 0 && t < T_FULL) ? Cb[c*T_FULL + t] : 0.f;
    }
    for (int idx = tid; idx < 6144; idx += 128){
        int c = idx / 192, rem = idx % 192;
        int o = rem / 3, k = rem % 3;
        ksh[k*2048 + c*64 + o] = KTb[idx];   // coalesced read, scattered smem store
    }
    __syncthreads();
    int o0 = (tid >> 5) * 8;   // 0..24 (lower-half channel base)
    int s0 = (tid & 31) * 4;
    float accL[8][4], accH[8][4];
    const float* Bb = &g_BS[(b*256 + layer*64)*L_];
    #pragma unroll
    for (int a = 0; a < 8; a++){
        float bl = Bb[(o0 + a)*L_ + l];
        float bh = Bb[(o0 + a + 32)*L_ + l];
        #pragma unroll
        for (int j = 0; j < 4; j++){ accL[a][j] = bl; accH[a][j] = bh; }
    }
    for (int c = 0; c < NCH; c++){
        float4 x4 = *(const float4*)&xs[c*132 + s0];
        float2 x2 = *(const float2*)&xs[c*132 + s0 + 4];
        float xv[6] = {x4.x, x4.y, x4.z, x4.w, x2.x, x2.y};
        #pragma unroll
        for (int k = 0; k < 3; k++){
            const float* kb = &ksh[k*2048 + c*64];
            float4 wl0 = *(const float4*)&kb[o0];
            float4 wl1 = *(const float4*)&kb[o0 + 4];
            float4 wh0 = *(const float4*)&kb[o0 + 32];
            float4 wh1 = *(const float4*)&kb[o0 + 36];
            float wl[8] = {wl0.x,wl0.y,wl0.z,wl0.w,wl1.x,wl1.y,wl1.z,wl1.w};
            float wh[8] = {wh0.x,wh0.y,wh0.z,wh0.w,wh1.x,wh1.y,wh1.z,wh1.w};
            #pragma unroll
            for (int j = 0; j < 4; j++){
                float x = xv[j + k];
                #pragma unroll
                for (int a = 0; a < 8; a++){
                    accL[a][j] += wl[a]*x;
                    accH[a][j] += wh[a]*x;
                }
            }
        }
    }
    float* Hb = &g_H[b*NCH*T_FULL];
    float* Ob = outp ? &outp[b*NCH*T_FULL] : Hb;
    #pragma unroll
    for (int a = 0; a < 8; a++){
        int oc = o0 + a;
        #pragma unroll
        for (int j = 0; j < 4; j++){
            int t = tseg + h0 + s0 + j;
            float sg = 1.f / (1.f + __expf(-accL[a][j]));
            float th = tanhf(accH[a][j]);
            Ob[oc*T_FULL + t] = sg*th + Hb[oc*T_FULL + t];
        }
    }
}

// ============================================================
extern "C" void kernel_launch(void* const* d_in, const int* in_sizes, int n_in,
                              void* d_out, int out_size){
    const float* hidden  = (const float*)d_in[0];
    const float* spec    = (const float*)d_in[1];
    const float* convt_w = (const float*)d_in[2];
    const float* convt_b = (const float*)d_in[3];
    const float* kp_in_w = (const float*)d_in[4];
    const float* kp_in_b = (const float*)d_in[5];
    const float* rb_w1   = (const float*)d_in[6];
    const float* rb_b1   = (const float*)d_in[7];
    const float* rb_w2   = (const float*)d_in[8];
    const float* rb_b2   = (const float*)d_in[9];
    const float* kern_w  = (const float*)d_in[10];
    const float* kern_b  = (const float*)d_in[11];
    const float* bias_w  = (const float*)d_in[12];
    const float* bias_b  = (const float*)d_in[13];
    const float* lvc_w   = (const float*)d_in[14];
    const float* lvc_b   = (const float*)d_in[15];

    // upsample hidden states
    k_convT<<<dim3(256, B_), 256>>>(hidden, convt_w, convt_b);

    // kernel predictor
    k_spec<<<dim3(B_, H_), 256>>>(spec, kp_in_w, kp_in_b);
    for (int i = 0; i < 3; i++){
        k_res<<<dim3(B_, H_), 256>>>(rb_w1 + i*12288, rb_b1 + i*64, 0);
        k_res<<<dim3(B_, H_), 256>>>(rb_w2 + i*12288, rb_b2 + i*64, 1);
    }
    k_kern_gemm<<<dim3(KC_/64, L_/64, B_), 256>>>(kern_w, kern_b);
    k_biasconv<<<dim3(B_, 256), 256>>>(bias_w, bias_b);

    // 4 LVC layers
    const int dil[4] = {1, 3, 9, 27};
    for (int i = 0; i < 4; i++){
        k_dconv<<<dim3(T_FULL/128, B_), 128>>>(lvc_w + i*3072, lvc_b + i*32, dil[i]);
        k_lvc<<<dim3(L_, 2, B_), 128>>>(i, (i == 3) ? (float*)d_out : nullptr);
    }
}

// round 4
// speedup vs baseline: 1.0138x; 1.0138x over previous
#include <cuda_runtime.h>
#include <cuda_bf16.h>
#include <cstdint>
#include <math.h>

#define B_     4
#define NCH    32
#define T_FULL 65536
#define T_IN   8192
#define L_     256
#define HOP_   256
#define H_     64
#define KC_    24576

// ---- scratch (device globals; no allocation allowed) ----
__device__ float g_H [B_*NCH*T_FULL];
__device__ float g_C [B_*NCH*T_FULL];
__device__ float g_F0[B_*H_*L_];
__device__ float g_F1[B_*H_*L_];
__device__ float g_KT[B_*L_*KC_];       // predicted kernels [n=b*L+l][kc]
__device__ float g_BS[B_*256*L_];       // predicted biases [b][bc][l]

__device__ __forceinline__ float lrelu(float x){ return x >= 0.f ? x : 0.2f*x; }

// ---- packed f32x2 helpers (FFMA2) ----
__device__ __forceinline__ uint64_t pack2f(float lo, float hi){
    uint64_t r; asm("mov.b64 %0, {%1, %2};" : "=l"(r) : "f"(lo), "f"(hi)); return r;
}
__device__ __forceinline__ uint64_t bcast2f(float x){ return pack2f(x, x); }
__device__ __forceinline__ void fma2(uint64_t& d, uint64_t a, uint64_t b){
    asm("fma.rn.f32x2 %0, %1, %2, %0;" : "+l"(d) : "l"(a), "l"(b));
}
__device__ __forceinline__ float2 unpack2f(uint64_t v){
    float2 r; asm("mov.b64 {%0, %1}, %2;" : "=f"(r.x), "=f"(r.y) : "l"(v)); return r;
}

// ============================================================
// K1: conv_transpose1d  (stride 8, K=16, pad 4)
// ============================================================
__global__ void k_convT(const float* __restrict__ x, const float* __restrict__ w,
                        const float* __restrict__ bias){
    int b  = blockIdx.y;
    int t0 = blockIdx.x * 256;
    int tid = threadIdx.x;
    int r = tid & 7, o = tid >> 3;
    __shared__ float xs[NCH*36];
    const float* xb = x + b*NCH*T_IN;
    int jbase = t0/8 - 1;
    for (int idx = tid; idx < NCH*34; idx += 256){
        int c = idx / 34, p = idx % 34;
        int j = jbase + p;
        xs[c*36 + p] = (j >= 0 && j < T_IN) ? xb[c*T_IN + j] : 0.f;
    }
    __syncthreads();
    float acc[32];
    float bv = bias[o];
    #pragma unroll
    for (int s = 0; s < 32; s++) acc[s] = bv;
    int off = (r + 4) & 7;
    int e   = (off >= 4) ? 1 : 0;
    for (int i = 0; i < NCH; i++){
        float w1 = w[(i*32 + o)*16 + r];
        float w2 = w[(i*32 + o)*16 + r + 8];
        const float* xr = &xs[i*36 + e];
        float vp = xr[0];
        #pragma unroll
        for (int s = 0; s < 32; s++){
            float v = xr[s + 1];
            acc[s] += w1*v + w2*vp;
            vp = v;
        }
    }
    float* out = &g_H[(b*NCH + o)*T_FULL];
    #pragma unroll
    for (int s = 0; s < 32; s++) out[t0 + off + 8*s] = acc[s];
}

// ============================================================
// K2: spectrogram input conv (100->64, K=5, pad 2)
// ============================================================
__global__ void k_spec(const float* __restrict__ spec, const float* __restrict__ w,
                       const float* __restrict__ bias){
    int b = blockIdx.x, lt = blockIdx.y;
    int tid = threadIdx.x;
    __shared__ float xs[100][38];
    __shared__ __align__(16) float ws[125][64];
    const float* sp = spec + b*100*L_;
    int l0 = lt*32;
    for (int idx = tid; idx < 100*36; idx += 256){
        int c = idx / 36, p = idx % 36;
        int t = l0 - 2 + p;
        xs[c][p] = (t >= 0 && t < L_) ? sp[c*L_ + t] : 0.f;
    }
    int hq = tid >> 5, li = tid & 31;
    uint64_t acc2[4];
    #pragma unroll
    for (int m = 0; m < 4; m++) acc2[m] = pack2f(bias[hq*8 + 2*m], bias[hq*8 + 2*m + 1]);
    for (int ch = 0; ch < 4; ch++){
        __syncthreads();
        for (int idx = tid; idx < 64*125; idx += 256){
            int h = idx / 125, ck = idx % 125;
            ws[ck][h] = w[h*500 + ch*125 + ck];
        }
        __syncthreads();
        for (int c2 = 0; c2 < 25; c2++){
            int c = ch*25 + c2;
            #pragma unroll
            for (int k = 0; k < 5; k++){
                uint64_t xb = bcast2f(xs[c][li + k]);
                const float* wr = &ws[c2*5 + k][hq*8];
                ulonglong2 wA = *(const ulonglong2*)wr;
                ulonglong2 wB = *(const ulonglong2*)(wr + 4);
                fma2(acc2[0], wA.x, xb);
                fma2(acc2[1], wA.y, xb);
                fma2(acc2[2], wB.x, xb);
                fma2(acc2[3], wB.y, xb);
            }
        }
    }
    int l = l0 + li;
    #pragma unroll
    for (int m = 0; m < 4; m++){
        float2 p = unpack2f(acc2[m]);
        g_F0[(b*H_ + hq*8 + 2*m    )*L_ + l] = p.x;
        g_F0[(b*H_ + hq*8 + 2*m + 1)*L_ + l] = p.y;
    }
}

// ============================================================
// K3: residual-block conv (64->64, K=3, pad 1), lrelu fused.
// ============================================================
__global__ void k_res(const float* __restrict__ w, const float* __restrict__ bias, int phase){
    int b = blockIdx.x, lt = blockIdx.y;
    int tid = threadIdx.x;
    __shared__ float xs[64][36];
    __shared__ __align__(16) float ws[192][64];
    const float* in = phase ? &g_F1[b*H_*L_] : &g_F0[b*H_*L_];
    int l0 = lt*32;
    for (int idx = tid; idx < 64*34; idx += 256){
        int c = idx / 34, p = idx % 34;
        int t = l0 - 1 + p;
        xs[c][p] = (t >= 0 && t < L_) ? in[c*L_ + t] : 0.f;
    }
    for (int idx = tid; idx < 64*192; idx += 256){
        int h = idx / 192, ck = idx % 192;
        ws[ck][h] = w[idx];
    }
    __syncthreads();
    int hq = tid >> 5, li = tid & 31;
    uint64_t acc2[4];
    #pragma unroll
    for (int m = 0; m < 4; m++) acc2[m] = pack2f(bias[hq*8 + 2*m], bias[hq*8 + 2*m + 1]);
    for (int c = 0; c < 64; c++){
        #pragma unroll
        for (int k = 0; k < 3; k++){
            uint64_t xb = bcast2f(xs[c][li + k]);
            const float* wr = &ws[c*3 + k][hq*8];
            ulonglong2 wA = *(const ulonglong2*)wr;
            ulonglong2 wB = *(const ulonglong2*)(wr + 4);
            fma2(acc2[0], wA.x, xb);
            fma2(acc2[1], wA.y, xb);
            fma2(acc2[2], wB.x, xb);
            fma2(acc2[3], wB.y, xb);
        }
    }
    int l = l0 + li;
    #pragma unroll
    for (int m = 0; m < 4; m++){
        float2 p = unpack2f(acc2[m]);
        int h0c = hq*8 + 2*m;
        float v0 = lrelu(p.x), v1 = lrelu(p.y);
        if (phase){
            g_F0[(b*H_ + h0c    )*L_ + l] = v0 + g_F0[(b*H_ + h0c    )*L_ + l];
            g_F0[(b*H_ + h0c + 1)*L_ + l] = v1 + g_F0[(b*H_ + h0c + 1)*L_ + l];
        } else {
            g_F1[(b*H_ + h0c    )*L_ + l] = v0;
            g_F1[(b*H_ + h0c + 1)*L_ + l] = v1;
        }
    }
}

// ============================================================
// K5: kern conv as GEMM (f32x2):  C[n][kc] = sum_r A[kc][r]*X[r][n]
//   128(kc) x 128(n) tile, BK=16, 8x8 micro-tile per thread.
// ============================================================
__global__ void __launch_bounds__(256)
k_kern_gemm(const float* __restrict__ A, const float* __restrict__ Ab){
    int kc0 = blockIdx.x * 128;
    int n0  = blockIdx.y * 128;
    int b   = n0 / L_;
    int l0w = n0 % L_;
    int tid = threadIdx.x;
    int ty = tid / 16, tx = tid % 16;
    __shared__ __align__(16) float As[16][128];
    __shared__ __align__(16) float Xs[16][128];
    const float* F = &g_F0[b*H_*L_];

    uint64_t acc2[4][8];
    #pragma unroll
    for (int m = 0; m < 4; m++){
        uint64_t bp = pack2f(Ab[kc0 + ty*8 + 2*m], Ab[kc0 + ty*8 + 2*m + 1]);
        #pragma unroll
        for (int j = 0; j < 8; j++) acc2[m][j] = bp;
    }

    int arow = tid >> 1, ac0 = (tid & 1) * 8;     // A-load mapping
    int xrr = tid >> 4, xl0 = (tid & 15) * 8;     // X-load mapping
    for (int bk = 0; bk < 12; bk++){
        int r0 = bk*16;
        float4 v0 = *(const float4*)&A[(kc0 + arow)*192 + r0 + ac0];
        float4 v1 = *(const float4*)&A[(kc0 + arow)*192 + r0 + ac0 + 4];
        As[ac0+0][arow] = v0.x; As[ac0+1][arow] = v0.y;
        As[ac0+2][arow] = v0.z; As[ac0+3][arow] = v0.w;
        As[ac0+4][arow] = v1.x; As[ac0+5][arow] = v1.y;
        As[ac0+6][arow] = v1.z; As[ac0+7][arow] = v1.w;
        {
            int r = r0 + xrr;
            int hh = r/3, k = r%3;
            #pragma unroll
            for (int q = 0; q < 8; q++){
                int t = l0w + xl0 + q + k - 1;
                Xs[xrr][xl0+q] = (t >= 0 && t < L_) ? F[hh*L_ + t] : 0.f;
            }
        }
        __syncthreads();
        #pragma unroll
        for (int kk = 0; kk < 16; kk++){
            ulonglong2 aA = *(const ulonglong2*)&As[kk][ty*8];
            ulonglong2 aB = *(const ulonglong2*)&As[kk][ty*8 + 4];
            uint64_t a2[4] = {aA.x, aA.y, aB.x, aB.y};
            float4 x0 = *(const float4*)&Xs[kk][tx*8];
            float4 x1 = *(const float4*)&Xs[kk][tx*8 + 4];
            uint64_t xb[8];
            xb[0] = bcast2f(x0.x); xb[1] = bcast2f(x0.y);
            xb[2] = bcast2f(x0.z); xb[3] = bcast2f(x0.w);
            xb[4] = bcast2f(x1.x); xb[5] = bcast2f(x1.y);
            xb[6] = bcast2f(x1.z); xb[7] = bcast2f(x1.w);
            #pragma unroll
            for (int j = 0; j < 8; j++)
                #pragma unroll
                for (int m = 0; m < 4; m++)
                    fma2(acc2[m][j], a2[m], xb[j]);
        }
        __syncthreads();
    }
    #pragma unroll
    for (int j = 0; j < 8; j++){
        int n = n0 + tx*8 + j;
        #pragma unroll
        for (int m = 0; m < 4; m++){
            float2 p = unpack2f(acc2[m][j]);
            *(float2*)&g_KT[n*KC_ + kc0 + ty*8 + 2*m] = p;
        }
    }
}

// ============================================================
// K6: bias conv (64->256, K=3, pad 1) -> g_BS[b][bc][l]
// ============================================================
__global__ void k_biasconv(const float* __restrict__ w, const float* __restrict__ bias){
    int b = blockIdx.x, lt = blockIdx.y, bct = blockIdx.z;
    int tid = threadIdx.x;
    __shared__ float xs[64][36];
    __shared__ __align__(16) float ws[192][64];
    const float* in = &g_F0[b*H_*L_];
    int l0 = lt*32, bc0 = bct*64;
    for (int idx = tid; idx < 64*34; idx += 256){
        int c = idx / 34, p = idx % 34;
        int t = l0 - 1 + p;
        xs[c][p] = (t >= 0 && t < L_) ? in[c*L_ + t] : 0.f;
    }
    for (int idx = tid; idx < 64*192; idx += 256){
        int h = idx / 192, ck = idx % 192;
        ws[ck][h] = w[(bc0 + h)*192 + ck];
    }
    __syncthreads();
    int hq = tid >> 5, li = tid & 31;
    uint64_t acc2[4];
    #pragma unroll
    for (int m = 0; m < 4; m++)
        acc2[m] = pack2f(bias[bc0 + hq*8 + 2*m], bias[bc0 + hq*8 + 2*m + 1]);
    for (int c = 0; c < 64; c++){
        #pragma unroll
        for (int k = 0; k < 3; k++){
            uint64_t xb = bcast2f(xs[c][li + k]);
            const float* wr = &ws[c*3 + k][hq*8];
            ulonglong2 wA = *(const ulonglong2*)wr;
            ulonglong2 wB = *(const ulonglong2*)(wr + 4);
            fma2(acc2[0], wA.x, xb);
            fma2(acc2[1], wA.y, xb);
            fma2(acc2[2], wB.x, xb);
            fma2(acc2[3], wB.y, xb);
        }
    }
    int l = l0 + li;
    #pragma unroll
    for (int m = 0; m < 4; m++){
        float2 p = unpack2f(acc2[m]);
        g_BS[(b*256 + bc0 + hq*8 + 2*m    )*L_ + l] = p.x;
        g_BS[(b*256 + bc0 + hq*8 + 2*m + 1)*L_ + l] = p.y;
    }
}

// ============================================================
// K7: fused lrelu -> dilated conv (32->32,K=3,pad d) -> lrelu into g_C
// ============================================================
__global__ void k_dconv(const float* __restrict__ w, const float* __restrict__ bias, int d){
    int b  = blockIdx.y;
    int t0 = blockIdx.x * 128;
    int tid = threadIdx.x;
    __shared__ float xs[NCH*184];
    __shared__ __align__(16) float ws[3*NCH*NCH];   // [k][i][o]
    int W = 128 + 2*d;
    const float* Hb = &g_H[b*NCH*T_FULL];
    for (int idx = tid; idx < NCH*W; idx += 128){
        int c = idx / W, p = idx % W;
        int t = t0 - d + p;
        xs[c*184 + p] = (t >= 0 && t < T_FULL) ? lrelu(Hb[c*T_FULL + t]) : 0.f;
    }
    for (int idx = tid; idx < 3072; idx += 128){
        int o = idx / 96, rem = idx % 96;
        int i = rem / 3, k = rem % 3;
        ws[k*1024 + i*32 + o] = w[idx];
    }
    __syncthreads();
    int o0 = (tid >> 5) * 8;
    int tl = (tid & 31) * 4;
    uint64_t acc2[4][4];
    #pragma unroll
    for (int m = 0; m < 4; m++){
        uint64_t bp = pack2f(bias[o0 + 2*m], bias[o0 + 2*m + 1]);
        #pragma unroll
        for (int j = 0; j < 4; j++) acc2[m][j] = bp;
    }
    for (int i = 0; i < NCH; i++){
        #pragma unroll
        for (int k = 0; k < 3; k++){
            uint64_t xb[4];
            #pragma unroll
            for (int j = 0; j < 4; j++) xb[j] = bcast2f(xs[i*184 + tl + j + k*d]);
            ulonglong2 wA = *(const ulonglong2*)&ws[k*1024 + i*32 + o0];
            ulonglong2 wB = *(const ulonglong2*)&ws[k*1024 + i*32 + o0 + 4];
            uint64_t w2[4] = {wA.x, wA.y, wB.x, wB.y};
            #pragma unroll
            for (int j = 0; j < 4; j++)
                #pragma unroll
                for (int m = 0; m < 4; m++)
                    fma2(acc2[m][j], w2[m], xb[j]);
        }
    }
    float* Cb = &g_C[b*NCH*T_FULL];
    #pragma unroll
    for (int m = 0; m < 4; m++)
        #pragma unroll
        for (int j = 0; j < 4; j++){
            float2 p = unpack2f(acc2[m][j]);
            Cb[(o0 + 2*m    )*T_FULL + t0 + tl + j] = lrelu(p.x);
            Cb[(o0 + 2*m + 1)*T_FULL + t0 + tl + j] = lrelu(p.y);
        }
}

// ============================================================
// K8: location-variable conv + bias + gating + residual (fused)
// ============================================================
__global__ void k_lvc(int layer, float* __restrict__ outp){
    int b  = blockIdx.z;
    int l  = blockIdx.x;
    int h0 = blockIdx.y * 128;
    int tid = threadIdx.x;
    __shared__ __align__(16) float xs[NCH*132];
    __shared__ __align__(16) float ksh[6144];   // [k][c][o]
    const float* Cb  = &g_C[b*NCH*T_FULL];
    const float* KTb = &g_KT[(b*L_ + l)*KC_ + layer*6144];
    int tseg = l*HOP_;
    for (int idx = tid; idx < NCH*130; idx += 128){
        int c = idx / 130, p = idx % 130;
        int t = tseg + h0 - 1 + p;
        xs[c*132 + p] = (t >= 0 && t < T_FULL) ? Cb[c*T_FULL + t] : 0.f;
    }
    for (int idx = tid; idx < 6144; idx += 128){
        int c = idx / 192, rem = idx % 192;
        int o = rem / 3, k = rem % 3;
        ksh[k*2048 + c*64 + o] = KTb[idx];
    }
    __syncthreads();
    int o0 = (tid >> 5) * 8;
    int s0 = (tid & 31) * 4;
    uint64_t accL2[4][4], accH2[4][4];
    const float* Bb = &g_BS[(b*256 + layer*64)*L_];
    #pragma unroll
    for (int m = 0; m < 4; m++){
        uint64_t bl = pack2f(Bb[(o0 + 2*m)*L_ + l], Bb[(o0 + 2*m + 1)*L_ + l]);
        uint64_t bh = pack2f(Bb[(o0 + 2*m + 32)*L_ + l], Bb[(o0 + 2*m + 33)*L_ + l]);
        #pragma unroll
        for (int j = 0; j < 4; j++){ accL2[m][j] = bl; accH2[m][j] = bh; }
    }
    for (int c = 0; c < NCH; c++){
        float4 x4 = *(const float4*)&xs[c*132 + s0];
        float2 x2 = *(const float2*)&xs[c*132 + s0 + 4];
        uint64_t xb[6];
        xb[0] = bcast2f(x4.x); xb[1] = bcast2f(x4.y); xb[2] = bcast2f(x4.z);
        xb[3] = bcast2f(x4.w); xb[4] = bcast2f(x2.x); xb[5] = bcast2f(x2.y);
        #pragma unroll
        for (int k = 0; k < 3; k++){
            const float* kb = &ksh[k*2048 + c*64];
            ulonglong2 wlA = *(const ulonglong2*)&kb[o0];
            ulonglong2 wlB = *(const ulonglong2*)&kb[o0 + 4];
            ulonglong2 whA = *(const ulonglong2*)&kb[o0 + 32];
            ulonglong2 whB = *(const ulonglong2*)&kb[o0 + 36];
            uint64_t wl2[4] = {wlA.x, wlA.y, wlB.x, wlB.y};
            uint64_t wh2[4] = {whA.x, whA.y, whB.x, whB.y};
            #pragma unroll
            for (int j = 0; j < 4; j++){
                uint64_t xx = xb[j + k];
                #pragma unroll
                for (int m = 0; m < 4; m++){
                    fma2(accL2[m][j], wl2[m], xx);
                    fma2(accH2[m][j], wh2[m], xx);
                }
            }
        }
    }
    float* Hb = &g_H[b*NCH*T_FULL];
    float* Ob = outp ? &outp[b*NCH*T_FULL] : Hb;
    #pragma unroll
    for (int m = 0; m < 4; m++){
        #pragma unroll
        for (int j = 0; j < 4; j++){
            int t = tseg + h0 + s0 + j;
            float2 pL = unpack2f(accL2[m][j]);
            float2 pH = unpack2f(accH2[m][j]);
            int oc0 = o0 + 2*m;
            float sg0 = 1.f / (1.f + __expf(-pL.x));
            float sg1 = 1.f / (1.f + __expf(-pL.y));
            float th0 = tanhf(pH.x);
            float th1 = tanhf(pH.y);
            Ob[(oc0    )*T_FULL + t] = sg0*th0 + Hb[(oc0    )*T_FULL + t];
            Ob[(oc0 + 1)*T_FULL + t] = sg1*th1 + Hb[(oc0 + 1)*T_FULL + t];
        }
    }
}

// ============================================================
extern "C" void kernel_launch(void* const* d_in, const int* in_sizes, int n_in,
                              void* d_out, int out_size){
    const float* hidden  = (const float*)d_in[0];
    const float* spec    = (const float*)d_in[1];
    const float* convt_w = (const float*)d_in[2];
    const float* convt_b = (const float*)d_in[3];
    const float* kp_in_w = (const float*)d_in[4];
    const float* kp_in_b = (const float*)d_in[5];
    const float* rb_w1   = (const float*)d_in[6];
    const float* rb_b1   = (const float*)d_in[7];
    const float* rb_w2   = (const float*)d_in[8];
    const float* rb_b2   = (const float*)d_in[9];
    const float* kern_w  = (const float*)d_in[10];
    const float* kern_b  = (const float*)d_in[11];
    const float* bias_w  = (const float*)d_in[12];
    const float* bias_b  = (const float*)d_in[13];
    const float* lvc_w   = (const float*)d_in[14];
    const float* lvc_b   = (const float*)d_in[15];

    // upsample hidden states
    k_convT<<<dim3(256, B_), 256>>>(hidden, convt_w, convt_b);

    // kernel predictor
    k_spec<<<dim3(B_, 8), 256>>>(spec, kp_in_w, kp_in_b);
    for (int i = 0; i < 3; i++){
        k_res<<<dim3(B_, 8), 256>>>(rb_w1 + i*12288, rb_b1 + i*64, 0);
        k_res<<<dim3(B_, 8), 256>>>(rb_w2 + i*12288, rb_b2 + i*64, 1);
    }
    k_kern_gemm<<<dim3(KC_/128, (B_*L_)/128), 256>>>(kern_w, kern_b);
    k_biasconv<<<dim3(B_, 8, 4), 256>>>(bias_w, bias_b);

    // 4 LVC layers
    const int dil[4] = {1, 3, 9, 27};
    for (int i = 0; i < 4; i++){
        k_dconv<<<dim3(T_FULL/128, B_), 128>>>(lvc_w + i*3072, lvc_b + i*32, dil[i]);
        k_lvc<<<dim3(L_, 2, B_), 128>>>(i, (i == 3) ? (float*)d_out : nullptr);
    }
}

// round 7
// speedup vs baseline: 1.0964x; 1.0815x over previous
#include <cuda_runtime.h>
#include <cstdint>
#include <math.h>

#define B_     4
#define NCH    32
#define T_FULL 65536
#define T_IN   8192
#define L_     256
#define HOP_   256
#define H_     64
#define KC_    24576

// ---- scratch (device globals; no allocation allowed) ----
__device__ float g_H [B_*NCH*T_FULL];
__device__ float g_C [B_*NCH*T_FULL];
__device__ float g_F0[B_*H_*L_];
__device__ float g_KT[B_*L_*KC_];       // predicted kernels [n=b*L+l][kc]
__device__ float g_BS[B_*256*L_];       // predicted biases [b][bc][l]

__device__ __forceinline__ float lrelu(float x){ return x >= 0.f ? x : 0.2f*x; }

// ---- packed f32x2 helpers ----
__device__ __forceinline__ uint64_t pack2f(float lo, float hi){
    uint64_t r; asm("mov.b64 %0, {%1, %2};" : "=l"(r) : "f"(lo), "f"(hi)); return r;
}
__device__ __forceinline__ uint64_t bcast2f(float x){ return pack2f(x, x); }
__device__ __forceinline__ void fma2(uint64_t& d, uint64_t a, uint64_t b){
    asm("fma.rn.f32x2 %0, %1, %2, %0;" : "+l"(d) : "l"(a), "l"(b));
}
__device__ __forceinline__ float2 unpack2f(uint64_t v){
    float2 r; asm("mov.b64 {%0, %1}, %2;" : "=f"(r.x), "=f"(r.y) : "l"(v)); return r;
}

// ============================================================
// K1: conv_transpose1d  (stride 8, K=16, pad 4)
// ============================================================
__global__ void k_convT(const float* __restrict__ x, const float* __restrict__ w,
                        const float* __restrict__ bias){
    int b  = blockIdx.y;
    int t0 = blockIdx.x * 256;
    int tid = threadIdx.x;
    int r = tid & 7, o = tid >> 3;
    __shared__ float xs[NCH*36];
    const float* xb = x + b*NCH*T_IN;
    int jbase = t0/8 - 1;
    for (int idx = tid; idx < NCH*34; idx += 256){
        int c = idx / 34, p = idx % 34;
        int j = jbase + p;
        xs[c*36 + p] = (j >= 0 && j < T_IN) ? xb[c*T_IN + j] : 0.f;
    }
    __syncthreads();
    float acc[32];
    float bv = bias[o];
    #pragma unroll
    for (int s = 0; s < 32; s++) acc[s] = bv;
    int off = (r + 4) & 7;
    int e   = (off >= 4) ? 1 : 0;
    for (int i = 0; i < NCH; i++){
        float w1 = w[(i*32 + o)*16 + r];
        float w2 = w[(i*32 + o)*16 + r + 8];
        const float* xr = &xs[i*36 + e];
        float vp = xr[0];
        #pragma unroll
        for (int s = 0; s < 32; s++){
            float v = xr[s + 1];
            acc[s] += w1*v + w2*vp;
            vp = v;
        }
    }
    float* out = &g_H[(b*NCH + o)*T_FULL];
    #pragma unroll
    for (int s = 0; s < 32; s++) out[t0 + off + 8*s] = acc[s];
}

// ============================================================
// K2: FUSED kernel predictor (spec conv + 3 residual blocks).
// grid (B, 8 l-splits of 32), 256 thr. Shrinking-validity halo:
// buffer pos p in [0,48) <-> global l = l0-8+p, smem stride 52,
// stored at q=p+2. Spec valid [2,45]; each K=3 conv shrinks 1/side.
// ============================================================
#define PRED_SMEM ((100*52 + 64*52 + 64*52 + 16000)*4)

__device__ __forceinline__ void pred_conv3(
    const float* src, float* dst, const float* rsd, float* wbuf,
    const float* __restrict__ wsrc, const float* __restrict__ bsrc,
    int plo, int phi, int l0, int hq, int pb, int tid){
    __syncthreads();
    for (int idx = tid; idx < 64*192; idx += 256){
        int h = idx/192, ck = idx%192;
        wbuf[ck*64 + h] = wsrc[h*192 + ck];
    }
    __syncthreads();
    uint64_t acc[2][3];
    #pragma unroll
    for (int m = 0; m < 2; m++){
        uint64_t bp = pack2f(bsrc[hq*4 + 2*m], bsrc[hq*4 + 2*m + 1]);
        acc[m][0]=bp; acc[m][1]=bp; acc[m][2]=bp;
    }
    for (int c = 0; c < 64; c++){
        float xv[5];
        #pragma unroll
        for (int m = 0; m < 5; m++) xv[m] = src[c*52 + pb + 1 + m];
        #pragma unroll
        for (int k = 0; k < 3; k++){
            ulonglong2 wp = *(const ulonglong2*)&wbuf[(c*3 + k)*64 + hq*4];
            #pragma unroll
            for (int j = 0; j < 3; j++){
                uint64_t xb = bcast2f(xv[j + k]);
                fma2(acc[0][j], wp.x, xb);
                fma2(acc[1][j], wp.y, xb);
            }
        }
    }
    #pragma unroll
    for (int m = 0; m < 2; m++)
    #pragma unroll
    for (int j = 0; j < 3; j++){
        int p = pb + j;
        if (p >= plo && p <= phi){
            int gl = l0 - 8 + p;
            bool ok = (gl >= 0 && gl < L_);
            float2 u = unpack2f(acc[m][j]);
            int ch0 = hq*4 + 2*m;
            float v0 = lrelu(u.x), v1 = lrelu(u.y);
            if (rsd){ v0 += rsd[ch0*52 + p + 2]; v1 += rsd[(ch0+1)*52 + p + 2]; }
            dst[ch0*52 + p + 2]     = ok ? v0 : 0.f;
            dst[(ch0+1)*52 + p + 2] = ok ? v1 : 0.f;
        }
    }
}

__global__ void __launch_bounds__(256)
k_pred(const float* __restrict__ spec,
       const float* __restrict__ kp_w, const float* __restrict__ kp_b,
       const float* __restrict__ rb_w1, const float* __restrict__ rb_b1,
       const float* __restrict__ rb_w2, const float* __restrict__ rb_b2){
    extern __shared__ float sm[];
    float* sspec = sm;                 // 100 x 52
    float* bufA  = sm + 100*52;        // 64 x 52
    float* bufB  = bufA + 64*52;
    float* wbuf  = bufB + 64*52;       // up to 16000
    int b = blockIdx.x, ls = blockIdx.y;
    int l0 = ls*32;
    int tid = threadIdx.x;
    int hq = tid >> 4;                 // 16 groups of 4 channels
    int pb = (tid & 15) * 3;           // 16 groups of 3 positions

    // stage spec input: q in [0,52) <-> gl = l0-10+q, zero-padded
    const float* sp = spec + b*100*L_;
    for (int idx = tid; idx < 100*52; idx += 256){
        int c = idx/52, q = idx%52;
        int gl = l0 - 10 + q;
        sspec[c*52 + q] = (gl >= 0 && gl < L_) ? sp[c*L_ + gl] : 0.f;
    }
    // --- spec conv (100->64, K=5, pad 2), no activation, valid p [2,45] ---
    uint64_t acc[2][3];
    #pragma unroll
    for (int m = 0; m < 2; m++){
        uint64_t bp = pack2f(kp_b[hq*4 + 2*m], kp_b[hq*4 + 2*m + 1]);
        acc[m][0]=bp; acc[m][1]=bp; acc[m][2]=bp;
    }
    for (int chunk = 0; chunk < 2; chunk++){
        __syncthreads();
        for (int idx = tid; idx < 16000; idx += 256){
            int h = idx/250, ck = idx%250;
            wbuf[ck*64 + h] = kp_w[h*500 + chunk*250 + ck];
        }
        __syncthreads();
        for (int c2 = 0; c2 < 50; c2++){
            int c = chunk*50 + c2;
            float xv[7];
            #pragma unroll
            for (int m = 0; m < 7; m++) xv[m] = sspec[c*52 + pb + m];
            #pragma unroll
            for (int k = 0; k < 5; k++){
                ulonglong2 wp = *(const ulonglong2*)&wbuf[(c2*5 + k)*64 + hq*4];
                #pragma unroll
                for (int j = 0; j < 3; j++){
                    uint64_t xb = bcast2f(xv[j + k]);
                    fma2(acc[0][j], wp.x, xb);
                    fma2(acc[1][j], wp.y, xb);
                }
            }
        }
    }
    #pragma unroll
    for (int m = 0; m < 2; m++)
    #pragma unroll
    for (int j = 0; j < 3; j++){
        int p = pb + j;
        if (p >= 2 && p <= 45){
            int gl = l0 - 8 + p;
            bool ok = (gl >= 0 && gl < L_);
            float2 u = unpack2f(acc[m][j]);
            int ch0 = hq*4 + 2*m;
            bufA[ch0*52 + p + 2]     = ok ? u.x : 0.f;
            bufA[(ch0+1)*52 + p + 2] = ok ? u.y : 0.f;
        }
    }
    // --- 3 residual blocks ---
    #pragma unroll 1
    for (int i = 0; i < 3; i++){
        pred_conv3(bufA, bufB, nullptr, wbuf, rb_w1 + i*12288, rb_b1 + i*64,
                   3+2*i, 44-2*i, l0, hq, pb, tid);
        pred_conv3(bufB, bufA, bufA,    wbuf, rb_w2 + i*12288, rb_b2 + i*64,
                   4+2*i, 43-2*i, l0, hq, pb, tid);
    }
    __syncthreads();
    // final store: p in [8,39] <-> l = l0..l0+31
    #pragma unroll
    for (int m = 0; m < 2; m++)
    #pragma unroll
    for (int j = 0; j < 3; j++){
        int p = pb + j;
        if (p >= 8 && p <= 39){
            int l = l0 - 8 + p;
            int ch0 = hq*4 + 2*m;
            g_F0[(b*H_ + ch0    )*L_ + l] = bufA[ch0*52 + p + 2];
            g_F0[(b*H_ + ch0 + 1)*L_ + l] = bufA[(ch0+1)*52 + p + 2];
        }
    }
}

// ============================================================
// K5: kern conv as GEMM (f32x2):  C[n][kc] = sum_r A[kc][r]*X[r][n]
// ============================================================
__global__ void __launch_bounds__(256)
k_kern_gemm(const float* __restrict__ A, const float* __restrict__ Ab){
    int kc0 = blockIdx.x * 128;
    int n0  = blockIdx.y * 128;
    int b   = n0 / L_;
    int l0w = n0 % L_;
    int tid = threadIdx.x;
    int ty = tid / 16, tx = tid % 16;
    __shared__ __align__(16) float As[16][128];
    __shared__ __align__(16) float Xs[16][128];
    const float* F = &g_F0[b*H_*L_];

    uint64_t acc2[4][8];
    #pragma unroll
    for (int m = 0; m < 4; m++){
        uint64_t bp = pack2f(Ab[kc0 + ty*8 + 2*m], Ab[kc0 + ty*8 + 2*m + 1]);
        #pragma unroll
        for (int j = 0; j < 8; j++) acc2[m][j] = bp;
    }
    int arow = tid >> 1, ac0 = (tid & 1) * 8;
    int xrr = tid >> 4, xl0 = (tid & 15) * 8;
    for (int bk = 0; bk < 12; bk++){
        int r0 = bk*16;
        float4 v0 = *(const float4*)&A[(kc0 + arow)*192 + r0 + ac0];
        float4 v1 = *(const float4*)&A[(kc0 + arow)*192 + r0 + ac0 + 4];
        As[ac0+0][arow] = v0.x; As[ac0+1][arow] = v0.y;
        As[ac0+2][arow] = v0.z; As[ac0+3][arow] = v0.w;
        As[ac0+4][arow] = v1.x; As[ac0+5][arow] = v1.y;
        As[ac0+6][arow] = v1.z; As[ac0+7][arow] = v1.w;
        {
            int r = r0 + xrr;
            int hh = r/3, k = r%3;
            #pragma unroll
            for (int q = 0; q < 8; q++){
                int t = l0w + xl0 + q + k - 1;
                Xs[xrr][xl0+q] = (t >= 0 && t < L_) ? F[hh*L_ + t] : 0.f;
            }
        }
        __syncthreads();
        #pragma unroll
        for (int kk = 0; kk < 16; kk++){
            ulonglong2 aA = *(const ulonglong2*)&As[kk][ty*8];
            ulonglong2 aB = *(const ulonglong2*)&As[kk][ty*8 + 4];
            uint64_t a2[4] = {aA.x, aA.y, aB.x, aB.y};
            float4 x0 = *(const float4*)&Xs[kk][tx*8];
            float4 x1 = *(const float4*)&Xs[kk][tx*8 + 4];
            uint64_t xb[8];
            xb[0] = bcast2f(x0.x); xb[1] = bcast2f(x0.y);
            xb[2] = bcast2f(x0.z); xb[3] = bcast2f(x0.w);
            xb[4] = bcast2f(x1.x); xb[5] = bcast2f(x1.y);
            xb[6] = bcast2f(x1.z); xb[7] = bcast2f(x1.w);
            #pragma unroll
            for (int j = 0; j < 8; j++)
                #pragma unroll
                for (int m = 0; m < 4; m++)
                    fma2(acc2[m][j], a2[m], xb[j]);
        }
        __syncthreads();
    }
    #pragma unroll
    for (int j = 0; j < 8; j++){
        int n = n0 + tx*8 + j;
        #pragma unroll
        for (int m = 0; m < 4; m++){
            float2 p = unpack2f(acc2[m][j]);
            *(float2*)&g_KT[n*KC_ + kc0 + ty*8 + 2*m] = p;
        }
    }
}

// ============================================================
// K6: bias conv (64->256, K=3, pad 1) -> g_BS[b][bc][l]
// ============================================================
__global__ void k_biasconv(const float* __restrict__ w, const float* __restrict__ bias){
    int b = blockIdx.x, lt = blockIdx.y, bct = blockIdx.z;
    int tid = threadIdx.x;
    __shared__ float xs[64][36];
    __shared__ __align__(16) float ws[192][64];
    const float* in = &g_F0[b*H_*L_];
    int l0 = lt*32, bc0 = bct*64;
    for (int idx = tid; idx < 64*34; idx += 256){
        int c = idx / 34, p = idx % 34;
        int t = l0 - 1 + p;
        xs[c][p] = (t >= 0 && t < L_) ? in[c*L_ + t] : 0.f;
    }
    for (int idx = tid; idx < 64*192; idx += 256){
        int h = idx / 192, ck = idx % 192;
        ws[ck][h] = w[(bc0 + h)*192 + ck];
    }
    __syncthreads();
    int hq = tid >> 5, li = tid & 31;
    uint64_t acc2[4];
    #pragma unroll
    for (int m = 0; m < 4; m++)
        acc2[m] = pack2f(bias[bc0 + hq*8 + 2*m], bias[bc0 + hq*8 + 2*m + 1]);
    for (int c = 0; c < 64; c++){
        #pragma unroll
        for (int k = 0; k < 3; k++){
            uint64_t xb = bcast2f(xs[c][li + k]);
            const float* wr = &ws[c*3 + k][hq*8];
            ulonglong2 wA = *(const ulonglong2*)wr;
            ulonglong2 wB = *(const ulonglong2*)(wr + 4);
            fma2(acc2[0], wA.x, xb);
            fma2(acc2[1], wA.y, xb);
            fma2(acc2[2], wB.x, xb);
            fma2(acc2[3], wB.y, xb);
        }
    }
    int l = l0 + li;
    #pragma unroll
    for (int m = 0; m < 4; m++){
        float2 p = unpack2f(acc2[m]);
        g_BS[(b*256 + bc0 + hq*8 + 2*m    )*L_ + l] = p.x;
        g_BS[(b*256 + bc0 + hq*8 + 2*m + 1)*L_ + l] = p.y;
    }
}

// ============================================================
// K7: fused lrelu -> dilated conv (32->32,K=3,pad D) -> lrelu into g_C
// 256 thr, 256-sample tiles, templated dilation (x-load CSE).
// ============================================================
#define DCONV_SMEM ((32*312 + 3072)*4)
template<int D>
__global__ void __launch_bounds__(256)
k_dconv(const float* __restrict__ w, const float* __restrict__ bias){
    extern __shared__ float sm[];
    float* xs = sm;           // 32 x 312 stride
    float* ws = sm + 32*312;  // [k][i][o] 3072
    int b  = blockIdx.y;
    int t0 = blockIdx.x * 256;
    int tid = threadIdx.x;
    const int W = 256 + 2*D;
    const float* Hb = &g_H[b*NCH*T_FULL];
    for (int idx = tid; idx < NCH*W; idx += 256){
        int c = idx / W, p = idx % W;
        int t = t0 - D + p;
        xs[c*312 + p] = (t >= 0 && t < T_FULL) ? lrelu(Hb[c*T_FULL + t]) : 0.f;
    }
    for (int idx = tid; idx < 3072; idx += 256){
        int o = idx / 96, rem = idx % 96;
        int i = rem / 3, k = rem % 3;
        ws[k*1024 + i*32 + o] = w[idx];
    }
    __syncthreads();
    int o0 = (tid >> 5) * 4;
    int s0 = (tid & 31) * 8;
    uint64_t acc[2][8];
    #pragma unroll
    for (int m = 0; m < 2; m++){
        uint64_t bp = pack2f(bias[o0 + 2*m], bias[o0 + 2*m + 1]);
        #pragma unroll
        for (int j = 0; j < 8; j++) acc[m][j] = bp;
    }
    for (int i = 0; i < NCH; i++){
        const float* xr = &xs[i*312 + s0];
        #pragma unroll
        for (int k = 0; k < 3; k++){
            ulonglong2 wp = *(const ulonglong2*)&ws[k*1024 + i*32 + o0];
            #pragma unroll
            for (int j = 0; j < 8; j++){
                uint64_t xb = bcast2f(xr[j + k*D]);
                fma2(acc[0][j], wp.x, xb);
                fma2(acc[1][j], wp.y, xb);
            }
        }
    }
    float* Cb = &g_C[b*NCH*T_FULL];
    #pragma unroll
    for (int cc = 0; cc < 4; cc++){
        float tmp[8];
        #pragma unroll
        for (int j = 0; j < 8; j++){
            float2 u = unpack2f(acc[cc>>1][j]);
            tmp[j] = lrelu((cc & 1) ? u.y : u.x);
        }
        float* dst = &Cb[(o0 + cc)*T_FULL + t0 + s0];
        *(float4*)dst     = make_float4(tmp[0], tmp[1], tmp[2], tmp[3]);
        *(float4*)(dst+4) = make_float4(tmp[4], tmp[5], tmp[6], tmp[7]);
    }
}

// ============================================================
// K8: location-variable conv + bias + gating + residual (fused)
// 256 thr, one block per (l, b): full 256-sample segment.
// ============================================================
#define LVC_SMEM ((32*264 + 6144)*4)
__global__ void __launch_bounds__(256)
k_lvc(int layer, float* __restrict__ outp){
    extern __shared__ float sm[];
    float* xs  = sm;            // 32 x 264 stride (258 used)
    float* ksh = sm + 32*264;   // [k][c][o] 6144
    int b = blockIdx.y, l = blockIdx.x;
    int tid = threadIdx.x;
    const float* Cb  = &g_C[b*NCH*T_FULL];
    const float* KTb = &g_KT[(b*L_ + l)*KC_ + layer*6144];
    int tseg = l*HOP_;
    for (int idx = tid; idx < 32*258; idx += 256){
        int c = idx / 258, p = idx % 258;
        int t = tseg - 1 + p;
        xs[c*264 + p] = (t >= 0 && t < T_FULL) ? Cb[c*T_FULL + t] : 0.f;
    }
    const float4* K4 = (const float4*)KTb;
    for (int i4 = tid; i4 < 1536; i4 += 256){
        float4 v = K4[i4];
        float vv[4] = {v.x, v.y, v.z, v.w};
        int base = i4*4;
        #pragma unroll
        for (int e = 0; e < 4; e++){
            int idx = base + e;
            int c = idx / 192, rem = idx % 192;
            int o = rem / 3, k = rem % 3;
            ksh[k*2048 + c*64 + o] = vv[e];
        }
    }
    __syncthreads();
    int o0 = (tid >> 5) * 4;     // 8 warps x 4 channels = 32
    int s0 = (tid & 31) * 8;     // 32 lanes x 8 samples = 256
    const float* Bb = &g_BS[(b*256 + layer*64)*L_];
    uint64_t accL[2][8], accH[2][8];
    #pragma unroll
    for (int m = 0; m < 2; m++){
        uint64_t bl = pack2f(Bb[(o0 + 2*m)*L_ + l],      Bb[(o0 + 2*m + 1)*L_ + l]);
        uint64_t bh = pack2f(Bb[(o0 + 2*m + 32)*L_ + l], Bb[(o0 + 2*m + 33)*L_ + l]);
        #pragma unroll
        for (int j = 0; j < 8; j++){ accL[m][j] = bl; accH[m][j] = bh; }
    }
    for (int c = 0; c < NCH; c++){
        const float* xr = &xs[c*264 + s0];
        float4 xa = *(const float4*)xr;
        float4 xbv = *(const float4*)(xr + 4);
        float2 xc = *(const float2*)(xr + 8);
        float xw[10] = {xa.x, xa.y, xa.z, xa.w, xbv.x, xbv.y, xbv.z, xbv.w, xc.x, xc.y};
        #pragma unroll
        for (int k = 0; k < 3; k++){
            ulonglong2 wl = *(const ulonglong2*)&ksh[k*2048 + c*64 + o0];
            ulonglong2 wh = *(const ulonglong2*)&ksh[k*2048 + c*64 + o0 + 32];
            #pragma unroll
            for (int j = 0; j < 8; j++){
                uint64_t x = bcast2f(xw[j + k]);
                fma2(accL[0][j], wl.x, x);
                fma2(accL[1][j], wl.y, x);
                fma2(accH[0][j], wh.x, x);
                fma2(accH[1][j], wh.y, x);
            }
        }
    }
    float* Hb = &g_H[b*NCH*T_FULL];
    float* Ob = outp ? &outp[b*NCH*T_FULL] : Hb;
    #pragma unroll
    for (int cc = 0; cc < 4; cc++){
        int oc = o0 + cc;
        const float* Hrow = &Hb[oc*T_FULL + tseg + s0];
        float4 r0 = *(const float4*)Hrow;
        float4 r1 = *(const float4*)(Hrow + 4);
        float rr[8] = {r0.x, r0.y, r0.z, r0.w, r1.x, r1.y, r1.z, r1.w};
        float tmp[8];
        #pragma unroll
        for (int j = 0; j < 8; j++){
            float2 uL = unpack2f(accL[cc>>1][j]);
            float2 uH = unpack2f(accH[cc>>1][j]);
            float aL = (cc & 1) ? uL.y : uL.x;
            float aH = (cc & 1) ? uH.y : uH.x;
            float sg = 1.f / (1.f + __expf(-aL));
            float th = tanhf(aH);
            tmp[j] = sg*th + rr[j];
        }
        float* dst = &Ob[oc*T_FULL + tseg + s0];
        *(float4*)dst     = make_float4(tmp[0], tmp[1], tmp[2], tmp[3]);
        *(float4*)(dst+4) = make_float4(tmp[4], tmp[5], tmp[6], tmp[7]);
    }
}

// ============================================================
extern "C" void kernel_launch(void* const* d_in, const int* in_sizes, int n_in,
                              void* d_out, int out_size){
    const float* hidden  = (const float*)d_in[0];
    const float* spec    = (const float*)d_in[1];
    const float* convt_w = (const float*)d_in[2];
    const float* convt_b = (const float*)d_in[3];
    const float* kp_in_w = (const float*)d_in[4];
    const float* kp_in_b = (const float*)d_in[5];
    const float* rb_w1   = (const float*)d_in[6];
    const float* rb_b1   = (const float*)d_in[7];
    const float* rb_w2   = (const float*)d_in[8];
    const float* rb_b2   = (const float*)d_in[9];
    const float* kern_w  = (const float*)d_in[10];
    const float* kern_b  = (const float*)d_in[11];
    const float* bias_w  = (const float*)d_in[12];
    const float* bias_b  = (const float*)d_in[13];
    const float* lvc_w   = (const float*)d_in[14];
    const float* lvc_b   = (const float*)d_in[15];

    cudaFuncSetAttribute(k_pred, cudaFuncAttributeMaxDynamicSharedMemorySize, PRED_SMEM);
    cudaFuncSetAttribute(k_lvc,  cudaFuncAttributeMaxDynamicSharedMemorySize, LVC_SMEM);
    cudaFuncSetAttribute(k_dconv<1>,  cudaFuncAttributeMaxDynamicSharedMemorySize, DCONV_SMEM);
    cudaFuncSetAttribute(k_dconv<3>,  cudaFuncAttributeMaxDynamicSharedMemorySize, DCONV_SMEM);
    cudaFuncSetAttribute(k_dconv<9>,  cudaFuncAttributeMaxDynamicSharedMemorySize, DCONV_SMEM);
    cudaFuncSetAttribute(k_dconv<27>, cudaFuncAttributeMaxDynamicSharedMemorySize, DCONV_SMEM);

    // 0: upsample hidden states
    k_convT<<<dim3(256, B_), 256>>>(hidden, convt_w, convt_b);
    // 1: fused kernel predictor
    k_pred<<<dim3(B_, 8), 256, PRED_SMEM>>>(spec, kp_in_w, kp_in_b,
                                            rb_w1, rb_b1, rb_w2, rb_b2);
    // 2: kern GEMM, 3: bias conv
    k_kern_gemm<<<dim3(KC_/128, (B_*L_)/128), 256>>>(kern_w, kern_b);
    k_biasconv<<<dim3(B_, 8, 4), 256>>>(bias_w, bias_b);

    // 4..11: four LVC layers
    for (int i = 0; i < 4; i++){
        const float* wi = lvc_w + i*3072;
        const float* bi = lvc_b + i*32;
        dim3 dg(T_FULL/256, B_);
        if      (i == 0) k_dconv<1> <<<dg, 256, DCONV_SMEM>>>(wi, bi);
        else if (i == 1) k_dconv<3> <<<dg, 256, DCONV_SMEM>>>(wi, bi);
        else if (i == 2) k_dconv<9> <<<dg, 256, DCONV_SMEM>>>(wi, bi);
        else             k_dconv<27><<<dg, 256, DCONV_SMEM>>>(wi, bi);
        k_lvc<<<dim3(L_, B_), 256, LVC_SMEM>>>(i, (i == 3) ? (float*)d_out : nullptr);
    }
}